// round 1
// baseline (speedup 1.0000x reference)
#include <cuda_runtime.h>

#define BATCH 8
#define SEQN  16384
#define CHN   256

// ---- scratch (static device globals; no allocation allowed) ----
__device__ float g_G [BATCH*CHN*CHN];   // Gram matrices X X^T
__device__ float g_s [BATCH*CHN];       // row sums X @ 1
__device__ float g_P [BATCH*CHN*CHN];   // Wq @ G
__device__ float g_qs[BATCH*CHN];       // Wq @ s
__device__ float g_ks[BATCH*CHN];       // Wk @ s
__device__ float g_cc[BATCH*CHN*CHN];   // scores -> softmax(+I)

// ============================================================
// zero accumulators (G, s) -- required because gram uses atomics
// ============================================================
__global__ void zero_kernel() {
    int i = blockIdx.x * 256 + threadIdx.x;
    if (i < BATCH*CHN*CHN) g_G[i] = 0.f;
    if (i < BATCH*CHN)     g_s[i] = 0.f;
}

// ============================================================
// Gram: G[b] = X_b X_b^T, X_b = [256, 16384] rows contiguous.
// 128x128 tile, 8x8 per thread, symmetric pairs (0,0),(0,1),(1,1),
// K split into 16 slices of 1024, fp32 atomic accumulation.
// Diagonal blocks also accumulate row sums s[b] for free.
// ============================================================
__global__ __launch_bounds__(256) void gram_kernel(const float* __restrict__ x) {
    const int pair = blockIdx.x;        // 0..2
    const int b    = blockIdx.y;        // 0..7
    const int slc  = blockIdx.z;        // 0..15
    const int rt = (pair == 2) ? 1 : 0;
    const int ct = (pair == 0) ? 0 : 1;

    const float* __restrict__ Ab = x + (size_t)b*CHN*SEQN + (size_t)(rt*128)*SEQN;
    const float* __restrict__ Bb = x + (size_t)b*CHN*SEQN + (size_t)(ct*128)*SEQN;

    __shared__ __align__(16) float As[8][132];
    __shared__ __align__(16) float Bs[8][132];

    const int t    = threadIdx.x;
    const int lrow = t >> 1;            // 0..127 (row of the tile this thread loads)
    const int kq   = (t & 1) * 4;       // 0 or 4 (k sub-offset)
    const int tx2  = t & 15;
    const int ty2  = t >> 4;

    float acc[8][8];
    #pragma unroll
    for (int i = 0; i < 8; i++)
        #pragma unroll
        for (int j = 0; j < 8; j++) acc[i][j] = 0.f;

    float rs = 0.f;

    const float* Aptr = Ab + (size_t)lrow*SEQN + kq;
    const float* Bptr = Bb + (size_t)lrow*SEQN + kq;

    const int kbeg = slc * 1024;
    for (int k0 = kbeg; k0 < kbeg + 1024; k0 += 8) {
        float4 va = *(const float4*)(Aptr + k0);
        float4 vb = *(const float4*)(Bptr + k0);
        rs += (va.x + va.y) + (va.z + va.w);
        As[kq+0][lrow] = va.x; As[kq+1][lrow] = va.y;
        As[kq+2][lrow] = va.z; As[kq+3][lrow] = va.w;
        Bs[kq+0][lrow] = vb.x; Bs[kq+1][lrow] = vb.y;
        Bs[kq+2][lrow] = vb.z; Bs[kq+3][lrow] = vb.w;
        __syncthreads();
        #pragma unroll
        for (int k = 0; k < 8; k++) {
            float4 a0 = *(const float4*)&As[k][ty2*4];
            float4 a1 = *(const float4*)&As[k][64 + ty2*4];
            float4 b0 = *(const float4*)&Bs[k][tx2*4];
            float4 b1 = *(const float4*)&Bs[k][64 + tx2*4];
            float ar[8] = {a0.x,a0.y,a0.z,a0.w,a1.x,a1.y,a1.z,a1.w};
            float br[8] = {b0.x,b0.y,b0.z,b0.w,b1.x,b1.y,b1.z,b1.w};
            #pragma unroll
            for (int i = 0; i < 8; i++)
                #pragma unroll
                for (int j = 0; j < 8; j++) acc[i][j] += ar[i]*br[j];
        }
        __syncthreads();
    }

    float* G = g_G + (size_t)b*CHN*CHN;
    int rid[8], cid[8];
    #pragma unroll
    for (int i = 0; i < 4; i++) {
        rid[i]   = rt*128 + ty2*4 + i;
        rid[4+i] = rt*128 + 64 + ty2*4 + i;
        cid[i]   = ct*128 + tx2*4 + i;
        cid[4+i] = ct*128 + 64 + tx2*4 + i;
    }
    #pragma unroll
    for (int i = 0; i < 8; i++)
        #pragma unroll
        for (int j = 0; j < 8; j++) {
            atomicAdd(&G[rid[i]*CHN + cid[j]], acc[i][j]);
            if (pair == 1) atomicAdd(&G[cid[j]*CHN + rid[i]], acc[i][j]);
        }

    // row sums: each (even,odd) thread pair covers one full row of this K slice
    rs += __shfl_xor_sync(0xffffffffu, rs, 1);
    if (rt == ct && (t & 1) == 0)
        atomicAdd(&g_s[b*CHN + rt*128 + lrow], rs);
}

// ============================================================
// P[b] = Wq @ G[b]   (64x64 tile, 4x4/thread; tiny: 128 blocks)
// ============================================================
__global__ __launch_bounds__(256) void pmat_kernel(const float* __restrict__ Wq) {
    const int ctile = blockIdx.x, rtile = blockIdx.y, b = blockIdx.z;
    const float* __restrict__ A  = Wq + rtile*64*CHN;                      // [o][c]
    const float* __restrict__ Bm = g_G + (size_t)b*CHN*CHN + ctile*64;     // [c][e]

    __shared__ __align__(16) float As[32][68];
    __shared__ __align__(16) float Bs[32][68];

    const int t = threadIdx.x, lane = t & 31, w = t >> 5;
    const int tx = t & 15, ty = t >> 4;

    float acc[4][4];
    #pragma unroll
    for (int i = 0; i < 4; i++)
        #pragma unroll
        for (int j = 0; j < 4; j++) acc[i][j] = 0.f;

    for (int k0 = 0; k0 < CHN; k0 += 32) {
        #pragma unroll
        for (int s = 0; s < 8; s++)
            As[lane][w + 8*s] = A[(w + 8*s)*CHN + k0 + lane];     // transpose load
        #pragma unroll
        for (int s = 0; s < 8; s++) {
            int idx = t + 256*s;
            int kk = idx >> 6, e = idx & 63;
            Bs[kk][e] = Bm[(size_t)(k0 + kk)*CHN + e];            // natural load
        }
        __syncthreads();
        #pragma unroll
        for (int k = 0; k < 32; k++) {
            float4 av = *(const float4*)&As[k][ty*4];
            float4 bv = *(const float4*)&Bs[k][tx*4];
            acc[0][0]+=av.x*bv.x; acc[0][1]+=av.x*bv.y; acc[0][2]+=av.x*bv.z; acc[0][3]+=av.x*bv.w;
            acc[1][0]+=av.y*bv.x; acc[1][1]+=av.y*bv.y; acc[1][2]+=av.y*bv.z; acc[1][3]+=av.y*bv.w;
            acc[2][0]+=av.z*bv.x; acc[2][1]+=av.z*bv.y; acc[2][2]+=av.z*bv.z; acc[2][3]+=av.z*bv.w;
            acc[3][0]+=av.w*bv.x; acc[3][1]+=av.w*bv.y; acc[3][2]+=av.w*bv.z; acc[3][3]+=av.w*bv.w;
        }
        __syncthreads();
    }
    float* P = g_P + (size_t)b*CHN*CHN;
    #pragma unroll
    for (int i = 0; i < 4; i++) {
        float4 v = make_float4(acc[i][0], acc[i][1], acc[i][2], acc[i][3]);
        *(float4*)&P[(size_t)(rtile*64 + ty*4 + i)*CHN + ctile*64 + tx*4] = v;
    }
}

// ============================================================
// qs = Wq @ s, ks = Wk @ s  (one warp per output row)
// ============================================================
__global__ void qsks_kernel(const float* __restrict__ Wq, const float* __restrict__ Wk) {
    const int b = blockIdx.y;
    const int o = blockIdx.x*8 + (threadIdx.x >> 5);
    const int lane = threadIdx.x & 31;
    const float* s = g_s + b*CHN;
    float aq = 0.f, ak = 0.f;
    for (int c = lane; c < CHN; c += 32) {
        float sv = s[c];
        aq += Wq[o*CHN + c] * sv;
        ak += Wk[o*CHN + c] * sv;
    }
    #pragma unroll
    for (int off = 16; off; off >>= 1) {
        aq += __shfl_xor_sync(0xffffffffu, aq, off);
        ak += __shfl_xor_sync(0xffffffffu, ak, off);
    }
    if (lane == 0) { g_qs[b*CHN + o] = aq; g_ks[b*CHN + o] = ak; }
}

// ============================================================
// scores = P @ Wk^T + qs*bk^T + bq*ks^T + N*bq*bk^T  -> g_cc
// ============================================================
__global__ __launch_bounds__(256) void scores_kernel(const float* __restrict__ Wk,
                                                     const float* __restrict__ bq,
                                                     const float* __restrict__ bk) {
    const int ctile = blockIdx.x, rtile = blockIdx.y, b = blockIdx.z;
    const float* __restrict__ A  = g_P + (size_t)b*CHN*CHN + rtile*64*CHN; // [c][e]
    const float* __restrict__ Bm = Wk + ctile*64*CHN;                      // [d][e]

    __shared__ __align__(16) float As[32][68];
    __shared__ __align__(16) float Bs[32][68];

    const int t = threadIdx.x, lane = t & 31, w = t >> 5;
    const int tx = t & 15, ty = t >> 4;

    float acc[4][4];
    #pragma unroll
    for (int i = 0; i < 4; i++)
        #pragma unroll
        for (int j = 0; j < 4; j++) acc[i][j] = 0.f;

    for (int k0 = 0; k0 < CHN; k0 += 32) {
        #pragma unroll
        for (int s = 0; s < 8; s++) {
            As[lane][w + 8*s] = A [(w + 8*s)*CHN + k0 + lane];
            Bs[lane][w + 8*s] = Bm[(w + 8*s)*CHN + k0 + lane];
        }
        __syncthreads();
        #pragma unroll
        for (int k = 0; k < 32; k++) {
            float4 av = *(const float4*)&As[k][ty*4];
            float4 bv = *(const float4*)&Bs[k][tx*4];
            acc[0][0]+=av.x*bv.x; acc[0][1]+=av.x*bv.y; acc[0][2]+=av.x*bv.z; acc[0][3]+=av.x*bv.w;
            acc[1][0]+=av.y*bv.x; acc[1][1]+=av.y*bv.y; acc[1][2]+=av.y*bv.z; acc[1][3]+=av.y*bv.w;
            acc[2][0]+=av.z*bv.x; acc[2][1]+=av.z*bv.y; acc[2][2]+=av.z*bv.z; acc[2][3]+=av.z*bv.w;
            acc[3][0]+=av.w*bv.x; acc[3][1]+=av.w*bv.y; acc[3][2]+=av.w*bv.z; acc[3][3]+=av.w*bv.w;
        }
        __syncthreads();
    }

    float* S = g_cc + (size_t)b*CHN*CHN;
    #pragma unroll
    for (int i = 0; i < 4; i++) {
        int r = rtile*64 + ty*4 + i;
        float qsr = g_qs[b*CHN + r];
        float bqr = bq[r];
        #pragma unroll
        for (int j = 0; j < 4; j++) {
            int d = ctile*64 + tx*4 + j;
            float v = acc[i][j] + qsr*bk[d] + bqr*(g_ks[b*CHN + d] + (float)SEQN * bk[d]);
            S[(size_t)r*CHN + d] = v;
        }
    }
}

// ============================================================
// row softmax over d, fold residual: cc' = softmax(scores) + I
// ============================================================
__global__ void softmax_kernel() {
    const int c = blockIdx.x, b = blockIdx.y;
    float* row = g_cc + (size_t)b*CHN*CHN + (size_t)c*CHN;
    const int d = threadIdx.x, lane = d & 31, w = d >> 5;
    __shared__ float smax[8];
    __shared__ float ssum[8];

    float v = row[d];
    float m = v;
    #pragma unroll
    for (int o = 16; o; o >>= 1) m = fmaxf(m, __shfl_xor_sync(0xffffffffu, m, o));
    if (lane == 0) smax[w] = m;
    __syncthreads();
    float M = smax[0];
    #pragma unroll
    for (int i = 1; i < 8; i++) M = fmaxf(M, smax[i]);

    float e = expf(v - M);
    float su = e;
    #pragma unroll
    for (int o = 16; o; o >>= 1) su += __shfl_xor_sync(0xffffffffu, su, o);
    if (lane == 0) ssum[w] = su;
    __syncthreads();
    float S = 0.f;
    #pragma unroll
    for (int i = 0; i < 8; i++) S += ssum[i];

    row[d] = e / S + ((d == c) ? 1.f : 0.f);
}

// ============================================================
// out[b] = Xin_b @ cc'[b]   (128x128 tile, 8x8/thread, K=256)
// ============================================================
__global__ __launch_bounds__(256) void out_kernel(const float* __restrict__ x,
                                                  float* __restrict__ out) {
    const int ctile = blockIdx.x;   // 0..1
    const int rtile = blockIdx.y;   // 0..127
    const int b     = blockIdx.z;
    const float* __restrict__ Ab = x   + (size_t)b*SEQN*CHN + (size_t)(rtile*128)*CHN;
    const float* __restrict__ Bb = g_cc + (size_t)b*CHN*CHN + ctile*128;

    __shared__ __align__(16) float As[8][132];
    __shared__ __align__(16) float Bs[8][132];

    const int t    = threadIdx.x;
    const int lrow = t >> 1;
    const int kq   = (t & 1) * 4;
    const int bkr  = t >> 5;        // 0..7: k-row for B load
    const int bd   = (t & 31) * 4;  // d offset for B load
    const int tx2  = t & 15;
    const int ty2  = t >> 4;

    float acc[8][8];
    #pragma unroll
    for (int i = 0; i < 8; i++)
        #pragma unroll
        for (int j = 0; j < 8; j++) acc[i][j] = 0.f;

    for (int k0 = 0; k0 < CHN; k0 += 8) {
        float4 va = *(const float4*)(Ab + (size_t)lrow*CHN + k0 + kq);
        float4 vb = *(const float4*)(Bb + (size_t)(k0 + bkr)*CHN + bd);
        As[kq+0][lrow] = va.x; As[kq+1][lrow] = va.y;
        As[kq+2][lrow] = va.z; As[kq+3][lrow] = va.w;
        *(float4*)&Bs[bkr][bd] = vb;
        __syncthreads();
        #pragma unroll
        for (int k = 0; k < 8; k++) {
            float4 a0 = *(const float4*)&As[k][ty2*4];
            float4 a1 = *(const float4*)&As[k][64 + ty2*4];
            float4 b0 = *(const float4*)&Bs[k][tx2*4];
            float4 b1 = *(const float4*)&Bs[k][64 + tx2*4];
            float ar[8] = {a0.x,a0.y,a0.z,a0.w,a1.x,a1.y,a1.z,a1.w};
            float br[8] = {b0.x,b0.y,b0.z,b0.w,b1.x,b1.y,b1.z,b1.w};
            #pragma unroll
            for (int i = 0; i < 8; i++)
                #pragma unroll
                for (int j = 0; j < 8; j++) acc[i][j] += ar[i]*br[j];
        }
        __syncthreads();
    }

    float* O = out + (size_t)b*SEQN*CHN + (size_t)(rtile*128)*CHN + ctile*128;
    #pragma unroll
    for (int i = 0; i < 8; i++) {
        int r = (i < 4) ? (ty2*4 + i) : (64 + ty2*4 + (i - 4));
        float4 v0 = make_float4(acc[i][0], acc[i][1], acc[i][2], acc[i][3]);
        float4 v1 = make_float4(acc[i][4], acc[i][5], acc[i][6], acc[i][7]);
        *(float4*)&O[(size_t)r*CHN + tx2*4]      = v0;
        *(float4*)&O[(size_t)r*CHN + 64 + tx2*4] = v1;
    }
}

// ============================================================
extern "C" void kernel_launch(void* const* d_in, const int* in_sizes, int n_in,
                              void* d_out, int out_size) {
    (void)in_sizes; (void)n_in; (void)out_size;
    const float* x  = (const float*)d_in[0];
    const float* Wq = (const float*)d_in[1];
    const float* bq = (const float*)d_in[2];
    const float* Wk = (const float*)d_in[3];
    const float* bk = (const float*)d_in[4];
    float* out = (float*)d_out;

    zero_kernel   <<<(BATCH*CHN*CHN + 255)/256, 256>>>();
    gram_kernel   <<<dim3(3, BATCH, 16), 256>>>(x);
    pmat_kernel   <<<dim3(4, 4, BATCH), 256>>>(Wq);
    qsks_kernel   <<<dim3(32, BATCH), 256>>>(Wq, Wk);
    scores_kernel <<<dim3(4, 4, BATCH), 256>>>(Wk, bq, bk);
    softmax_kernel<<<dim3(CHN, BATCH), 256>>>();
    out_kernel    <<<dim3(2, 128, BATCH), 256>>>(x, out);
}

// round 3
// speedup vs baseline: 1.8001x; 1.8001x over previous
#include <cuda_runtime.h>
#include <cuda_bf16.h>

#define BATCH 8
#define SEQN  16384
#define CHN   256
#define NELEM (BATCH*SEQN*CHN)

// ---- scratch (static device globals; no allocation allowed) ----
__device__ __nv_bfloat16 g_xhi[NELEM];            // bf16 hi part of x
__device__ __nv_bfloat16 g_xlo[NELEM];            // bf16 lo part of x
__device__ float g_G [BATCH*CHN*CHN];             // Gram X X^T (fp32, atomics)
__device__ float g_s [BATCH*CHN];                 // row sums X @ 1
__device__ float g_P [BATCH*CHN*CHN];             // Wq @ G
__device__ float g_qs[BATCH*CHN];                 // Wq @ s
__device__ float g_ks[BATCH*CHN];                 // Wk @ s
__device__ float g_cc[BATCH*CHN*CHN];             // scores (fp32 workspace)
__device__ __nv_bfloat16 g_ccT_hi[BATCH*CHN*CHN]; // (softmax+I)^T split bf16
__device__ __nv_bfloat16 g_ccT_lo[BATCH*CHN*CHN];

// ============================================================
// helpers (all baseline PTX: sm_80-level, legal in compute_103)
// ============================================================
__device__ __forceinline__ unsigned smem_u32(const void* p) {
    return (unsigned)__cvta_generic_to_shared(p);
}
__device__ __forceinline__ void cp16(unsigned dst, const void* src) {
    asm volatile("cp.async.cg.shared.global [%0], [%1], 16;" :: "r"(dst), "l"(src) : "memory");
}
#define CP_COMMIT() asm volatile("cp.async.commit_group;" ::: "memory")
template<int N> __device__ __forceinline__ void cp_wait() {
    asm volatile("cp.async.wait_group %0;" :: "n"(N) : "memory");
}
__device__ __forceinline__ void ldsm4(unsigned addr, unsigned& r0, unsigned& r1,
                                      unsigned& r2, unsigned& r3) {
    asm volatile("ldmatrix.sync.aligned.m8n8.x4.shared.b16 {%0,%1,%2,%3}, [%4];"
                 : "=r"(r0), "=r"(r1), "=r"(r2), "=r"(r3) : "r"(addr));
}
#define MMA_BF16(acc, a, b0v, b1v) \
    asm volatile("mma.sync.aligned.m16n8k16.row.col.f32.bf16.bf16.f32 " \
                 "{%0,%1,%2,%3},{%4,%5,%6,%7},{%8,%9},{%0,%1,%2,%3};" \
                 : "+f"((acc)[0]), "+f"((acc)[1]), "+f"((acc)[2]), "+f"((acc)[3]) \
                 : "r"((a)[0]), "r"((a)[1]), "r"((a)[2]), "r"((a)[3]), \
                   "r"(b0v), "r"(b1v))

// smem tile geometry: 128 rows x 32 bf16 k, row stride 80B (64B data + 16B pad)
#define ROW_B   80
#define TILE_B  (128*ROW_B)           // 10240
#define OFF_AHI 0
#define OFF_ALO (1*TILE_B)
#define OFF_BHI (2*TILE_B)
#define OFF_BLO (3*TILE_B)
#define STAGE_B (4*TILE_B)            // 40960
#define SMEM_MMA (2*STAGE_B)          // 81920

// load one 128x32 bf16 tile (2 chunks of 16B per thread)
__device__ __forceinline__ void load_tile(unsigned dst, const __nv_bfloat16* __restrict__ src,
                                          size_t stride, int k0, int t) {
    #pragma unroll
    for (int i = 0; i < 2; i++) {
        int c = t + 256*i;
        int row = c >> 2, kc = c & 3;
        cp16(dst + row*ROW_B + kc*16, src + (size_t)row*stride + k0 + kc*8);
    }
}
__device__ __forceinline__ void load_stage(unsigned base, int t,
        const __nv_bfloat16* Ah, const __nv_bfloat16* Al, size_t sA,
        const __nv_bfloat16* Bh, const __nv_bfloat16* Bl, size_t sB, int k0) {
    load_tile(base + OFF_AHI, Ah, sA, k0, t);
    load_tile(base + OFF_ALO, Al, sA, k0, t);
    load_tile(base + OFF_BHI, Bh, sB, k0, t);
    load_tile(base + OFF_BLO, Bl, sB, k0, t);
    CP_COMMIT();
}

// compute one BK=32 stage: warp tile 32x64 at (m0,n0); acc[2][8][4]
__device__ __forceinline__ void compute_stage(unsigned base, int m0, int n0, int lane,
                                              float acc[2][8][4]) {
    const int lrow = lane & 15;
    const int lhalf = lane >> 4;
    #pragma unroll
    for (int ks = 0; ks < 2; ks++) {
        const unsigned kb = ks*32 + lhalf*16;
        unsigned ah[2][4], al[2][4];
        #pragma unroll
        for (int mt = 0; mt < 2; mt++) {
            unsigned r = (m0 + mt*16 + lrow)*ROW_B + kb;
            ldsm4(base + OFF_AHI + r, ah[mt][0], ah[mt][1], ah[mt][2], ah[mt][3]);
            ldsm4(base + OFF_ALO + r, al[mt][0], al[mt][1], al[mt][2], al[mt][3]);
        }
        unsigned bh[4][4], bl[4][4];
        #pragma unroll
        for (int np = 0; np < 4; np++) {
            unsigned r = (n0 + np*16 + lrow)*ROW_B + kb;
            ldsm4(base + OFF_BHI + r, bh[np][0], bh[np][1], bh[np][2], bh[np][3]);
            ldsm4(base + OFF_BLO + r, bl[np][0], bl[np][1], bl[np][2], bl[np][3]);
        }
        #pragma unroll
        for (int mt = 0; mt < 2; mt++)
            #pragma unroll
            for (int np = 0; np < 4; np++) {
                // n-tile 2*np   : B regs {r0, r2}
                MMA_BF16(acc[mt][2*np],   ah[mt], bh[np][0], bh[np][2]);
                MMA_BF16(acc[mt][2*np],   ah[mt], bl[np][0], bl[np][2]);
                MMA_BF16(acc[mt][2*np],   al[mt], bh[np][0], bh[np][2]);
                // n-tile 2*np+1 : B regs {r1, r3}
                MMA_BF16(acc[mt][2*np+1], ah[mt], bh[np][1], bh[np][3]);
                MMA_BF16(acc[mt][2*np+1], ah[mt], bl[np][1], bl[np][3]);
                MMA_BF16(acc[mt][2*np+1], al[mt], bh[np][1], bh[np][3]);
            }
    }
}

// ============================================================
// zero accumulators (G, s)
// ============================================================
__global__ void zero_kernel() {
    int i = blockIdx.x * 256 + threadIdx.x;
    if (i < BATCH*CHN*CHN) g_G[i] = 0.f;
    if (i < BATCH*CHN)     g_s[i] = 0.f;
}

// ============================================================
// convert: x fp32 -> (hi, lo) bf16 split; fused row sums
// ============================================================
__device__ __forceinline__ unsigned pack2(float a, float b, float* ra, float* rb) {
    __nv_bfloat16 ha = __float2bfloat16(a);
    __nv_bfloat16 hb = __float2bfloat16(b);
    *ra = a - __bfloat162float(ha);
    *rb = b - __bfloat162float(hb);
    __nv_bfloat162 p; p.x = ha; p.y = hb;
    return *reinterpret_cast<unsigned*>(&p);
}
__device__ __forceinline__ unsigned pack2lo(float a, float b) {
    __nv_bfloat162 p; p.x = __float2bfloat16(a); p.y = __float2bfloat16(b);
    return *reinterpret_cast<unsigned*>(&p);
}

__global__ __launch_bounds__(256) void convert_kernel(const float* __restrict__ x) {
    size_t i = ((size_t)blockIdx.x * 256 + threadIdx.x) * 8;
    float4 v0 = *(const float4*)(x + i);
    float4 v1 = *(const float4*)(x + i + 4);
    float r[8];
    uint4 hi, lo;
    hi.x = pack2(v0.x, v0.y, &r[0], &r[1]);
    hi.y = pack2(v0.z, v0.w, &r[2], &r[3]);
    hi.z = pack2(v1.x, v1.y, &r[4], &r[5]);
    hi.w = pack2(v1.z, v1.w, &r[6], &r[7]);
    lo.x = pack2lo(r[0], r[1]);
    lo.y = pack2lo(r[2], r[3]);
    lo.z = pack2lo(r[4], r[5]);
    lo.w = pack2lo(r[6], r[7]);
    *(uint4*)(g_xhi + i) = hi;
    *(uint4*)(g_xlo + i) = lo;

    float rs = ((v0.x + v0.y) + (v0.z + v0.w)) + ((v1.x + v1.y) + (v1.z + v1.w));
    #pragma unroll
    for (int o = 16; o; o >>= 1) rs += __shfl_xor_sync(0xffffffffu, rs, o);
    if ((threadIdx.x & 31) == 0) atomicAdd(&g_s[i >> 14], rs);
}

// ============================================================
// Gram: G[b] += Xtile @ Xtile^T via mma.sync, split bf16.
// grid (3 pairs, 8 b, 16 kslices); symmetric pair (0,1) mirrored.
// ============================================================
__global__ __launch_bounds__(256, 1) void gram_mma_kernel() {
    extern __shared__ __align__(128) char smem[];
    const unsigned sb = smem_u32(smem);
    const int t = threadIdx.x, lane = t & 31, warp = t >> 5;
    const int pair = blockIdx.x, b = blockIdx.y, slc = blockIdx.z;
    const int rt = (pair == 2) ? 1 : 0;
    const int ct = (pair == 0) ? 0 : 1;
    const int kbase = slc * 1024;

    const __nv_bfloat16* Ah = g_xhi + ((size_t)b*CHN + rt*128) * SEQN;
    const __nv_bfloat16* Al = g_xlo + ((size_t)b*CHN + rt*128) * SEQN;
    const __nv_bfloat16* Bh = g_xhi + ((size_t)b*CHN + ct*128) * SEQN;
    const __nv_bfloat16* Bl = g_xlo + ((size_t)b*CHN + ct*128) * SEQN;

    const int m0 = (warp >> 1) * 32;   // 4 warps over M
    const int n0 = (warp & 1) * 64;    // 2 warps over N

    float acc[2][8][4];
    #pragma unroll
    for (int i = 0; i < 2; i++)
        #pragma unroll
        for (int j = 0; j < 8; j++)
            #pragma unroll
            for (int k = 0; k < 4; k++) acc[i][j][k] = 0.f;

    load_stage(sb, t, Ah, Al, SEQN, Bh, Bl, SEQN, kbase);
    #pragma unroll 1
    for (int s = 0; s < 32; s++) {
        if (s + 1 < 32) {
            load_stage(sb + ((s+1)&1)*STAGE_B, t, Ah, Al, SEQN, Bh, Bl, SEQN,
                       kbase + (s+1)*32);
            cp_wait<1>();
        } else cp_wait<0>();
        __syncthreads();
        compute_stage(sb + (s&1)*STAGE_B, m0, n0, lane, acc);
        __syncthreads();
    }

    // epilogue: atomic accumulate (+ mirror for off-diagonal pair)
    float* G = g_G + (size_t)b*CHN*CHN;
    const int gid = lane >> 2, qid = lane & 3;
    #pragma unroll
    for (int mt = 0; mt < 2; mt++)
        #pragma unroll
        for (int nt = 0; nt < 8; nt++) {
            int r0 = rt*128 + m0 + mt*16 + gid;
            int c0 = ct*128 + n0 + nt*8 + qid*2;
            float* a = acc[mt][nt];
            atomicAdd(&G[(size_t)r0*CHN + c0],       a[0]);
            atomicAdd(&G[(size_t)r0*CHN + c0 + 1],   a[1]);
            atomicAdd(&G[(size_t)(r0+8)*CHN + c0],   a[2]);
            atomicAdd(&G[(size_t)(r0+8)*CHN + c0+1], a[3]);
            if (pair == 1) {
                atomicAdd(&G[(size_t)c0*CHN + r0],       a[0]);
                atomicAdd(&G[(size_t)(c0+1)*CHN + r0],   a[1]);
                atomicAdd(&G[(size_t)c0*CHN + r0 + 8],   a[2]);
                atomicAdd(&G[(size_t)(c0+1)*CHN + r0+8], a[3]);
            }
        }
}

// ============================================================
// out: out[b, mt*128:+128, ct*128:+128] = Xin_tile @ ccT_tile (K=256)
// grid (2 ct, 128 mt, 8 b)
// ============================================================
__global__ __launch_bounds__(256, 1) void out_mma_kernel(float* __restrict__ out) {
    extern __shared__ __align__(128) char smem[];
    const unsigned sb = smem_u32(smem);
    const int t = threadIdx.x, lane = t & 31, warp = t >> 5;
    const int ct = blockIdx.x, mt_blk = blockIdx.y, b = blockIdx.z;

    const __nv_bfloat16* Ah = g_xhi    + ((size_t)b*SEQN + mt_blk*128) * CHN;
    const __nv_bfloat16* Al = g_xlo    + ((size_t)b*SEQN + mt_blk*128) * CHN;
    const __nv_bfloat16* Bh = g_ccT_hi + ((size_t)b*CHN + ct*128) * CHN;
    const __nv_bfloat16* Bl = g_ccT_lo + ((size_t)b*CHN + ct*128) * CHN;

    const int m0 = (warp >> 1) * 32;
    const int n0 = (warp & 1) * 64;

    float acc[2][8][4];
    #pragma unroll
    for (int i = 0; i < 2; i++)
        #pragma unroll
        for (int j = 0; j < 8; j++)
            #pragma unroll
            for (int k = 0; k < 4; k++) acc[i][j][k] = 0.f;

    load_stage(sb, t, Ah, Al, CHN, Bh, Bl, CHN, 0);
    #pragma unroll 1
    for (int s = 0; s < 8; s++) {
        if (s + 1 < 8) {
            load_stage(sb + ((s+1)&1)*STAGE_B, t, Ah, Al, CHN, Bh, Bl, CHN, (s+1)*32);
            cp_wait<1>();
        } else cp_wait<0>();
        __syncthreads();
        compute_stage(sb + (s&1)*STAGE_B, m0, n0, lane, acc);
        __syncthreads();
    }

    float* O = out + ((size_t)b*SEQN + mt_blk*128) * CHN + ct*128;
    const int gid = lane >> 2, qid = lane & 3;
    #pragma unroll
    for (int mt = 0; mt < 2; mt++)
        #pragma unroll
        for (int nt = 0; nt < 8; nt++) {
            int r0 = m0 + mt*16 + gid;
            int c0 = n0 + nt*8 + qid*2;
            float* a = acc[mt][nt];
            *(float2*)&O[(size_t)r0*CHN + c0]     = make_float2(a[0], a[1]);
            *(float2*)&O[(size_t)(r0+8)*CHN + c0] = make_float2(a[2], a[3]);
        }
}

// ============================================================
// P[b] = Wq @ G[b]   (64x64 tile, 4x4/thread)
// ============================================================
__global__ __launch_bounds__(256) void pmat_kernel(const float* __restrict__ Wq) {
    const int ctile = blockIdx.x, rtile = blockIdx.y, b = blockIdx.z;
    const float* __restrict__ A  = Wq + rtile*64*CHN;
    const float* __restrict__ Bm = g_G + (size_t)b*CHN*CHN + ctile*64;

    __shared__ __align__(16) float As[32][68];
    __shared__ __align__(16) float Bs[32][68];

    const int t = threadIdx.x, lane = t & 31, w = t >> 5;
    const int tx = t & 15, ty = t >> 4;

    float acc[4][4];
    #pragma unroll
    for (int i = 0; i < 4; i++)
        #pragma unroll
        for (int j = 0; j < 4; j++) acc[i][j] = 0.f;

    for (int k0 = 0; k0 < CHN; k0 += 32) {
        #pragma unroll
        for (int s = 0; s < 8; s++)
            As[lane][w + 8*s] = A[(w + 8*s)*CHN + k0 + lane];
        #pragma unroll
        for (int s = 0; s < 8; s++) {
            int idx = t + 256*s;
            int kk = idx >> 6, e = idx & 63;
            Bs[kk][e] = Bm[(size_t)(k0 + kk)*CHN + e];
        }
        __syncthreads();
        #pragma unroll
        for (int k = 0; k < 32; k++) {
            float4 av = *(const float4*)&As[k][ty*4];
            float4 bv = *(const float4*)&Bs[k][tx*4];
            acc[0][0]+=av.x*bv.x; acc[0][1]+=av.x*bv.y; acc[0][2]+=av.x*bv.z; acc[0][3]+=av.x*bv.w;
            acc[1][0]+=av.y*bv.x; acc[1][1]+=av.y*bv.y; acc[1][2]+=av.y*bv.z; acc[1][3]+=av.y*bv.w;
            acc[2][0]+=av.z*bv.x; acc[2][1]+=av.z*bv.y; acc[2][2]+=av.z*bv.z; acc[2][3]+=av.z*bv.w;
            acc[3][0]+=av.w*bv.x; acc[3][1]+=av.w*bv.y; acc[3][2]+=av.w*bv.z; acc[3][3]+=av.w*bv.w;
        }
        __syncthreads();
    }
    float* P = g_P + (size_t)b*CHN*CHN;
    #pragma unroll
    for (int i = 0; i < 4; i++) {
        float4 v = make_float4(acc[i][0], acc[i][1], acc[i][2], acc[i][3]);
        *(float4*)&P[(size_t)(rtile*64 + ty*4 + i)*CHN + ctile*64 + tx*4] = v;
    }
}

// ============================================================
// qs = Wq @ s, ks = Wk @ s
// ============================================================
__global__ void qsks_kernel(const float* __restrict__ Wq, const float* __restrict__ Wk) {
    const int b = blockIdx.y;
    const int o = blockIdx.x*8 + (threadIdx.x >> 5);
    const int lane = threadIdx.x & 31;
    const float* s = g_s + b*CHN;
    float aq = 0.f, ak = 0.f;
    for (int c = lane; c < CHN; c += 32) {
        float sv = s[c];
        aq += Wq[o*CHN + c] * sv;
        ak += Wk[o*CHN + c] * sv;
    }
    #pragma unroll
    for (int off = 16; off; off >>= 1) {
        aq += __shfl_xor_sync(0xffffffffu, aq, off);
        ak += __shfl_xor_sync(0xffffffffu, ak, off);
    }
    if (lane == 0) { g_qs[b*CHN + o] = aq; g_ks[b*CHN + o] = ak; }
}

// ============================================================
// scores = P @ Wk^T + qs*bk^T + bq*ks^T + N*bq*bk^T  -> g_cc
// ============================================================
__global__ __launch_bounds__(256) void scores_kernel(const float* __restrict__ Wk,
                                                     const float* __restrict__ bq,
                                                     const float* __restrict__ bk) {
    const int ctile = blockIdx.x, rtile = blockIdx.y, b = blockIdx.z;
    const float* __restrict__ A  = g_P + (size_t)b*CHN*CHN + rtile*64*CHN;
    const float* __restrict__ Bm = Wk + ctile*64*CHN;

    __shared__ __align__(16) float As[32][68];
    __shared__ __align__(16) float Bs[32][68];

    const int t = threadIdx.x, lane = t & 31, w = t >> 5;
    const int tx = t & 15, ty = t >> 4;

    float acc[4][4];
    #pragma unroll
    for (int i = 0; i < 4; i++)
        #pragma unroll
        for (int j = 0; j < 4; j++) acc[i][j] = 0.f;

    for (int k0 = 0; k0 < CHN; k0 += 32) {
        #pragma unroll
        for (int s = 0; s < 8; s++) {
            As[lane][w + 8*s] = A [(w + 8*s)*CHN + k0 + lane];
            Bs[lane][w + 8*s] = Bm[(w + 8*s)*CHN + k0 + lane];
        }
        __syncthreads();
        #pragma unroll
        for (int k = 0; k < 32; k++) {
            float4 av = *(const float4*)&As[k][ty*4];
            float4 bv = *(const float4*)&Bs[k][tx*4];
            acc[0][0]+=av.x*bv.x; acc[0][1]+=av.x*bv.y; acc[0][2]+=av.x*bv.z; acc[0][3]+=av.x*bv.w;
            acc[1][0]+=av.y*bv.x; acc[1][1]+=av.y*bv.y; acc[1][2]+=av.y*bv.z; acc[1][3]+=av.y*bv.w;
            acc[2][0]+=av.z*bv.x; acc[2][1]+=av.z*bv.y; acc[2][2]+=av.z*bv.z; acc[2][3]+=av.z*bv.w;
            acc[3][0]+=av.w*bv.x; acc[3][1]+=av.w*bv.y; acc[3][2]+=av.w*bv.z; acc[3][3]+=av.w*bv.w;
        }
        __syncthreads();
    }

    float* S = g_cc + (size_t)b*CHN*CHN;
    #pragma unroll
    for (int i = 0; i < 4; i++) {
        int r = rtile*64 + ty*4 + i;
        float qsr = g_qs[b*CHN + r];
        float bqr = bq[r];
        #pragma unroll
        for (int j = 0; j < 4; j++) {
            int d = ctile*64 + tx*4 + j;
            float v = acc[i][j] + qsr*bk[d] + bqr*(g_ks[b*CHN + d] + (float)SEQN * bk[d]);
            S[(size_t)r*CHN + d] = v;
        }
    }
}

// ============================================================
// softmax rows; fold residual (+I); emit transposed bf16 split ccT[d][c]
// ============================================================
__global__ void softmax_kernel() {
    const int c = blockIdx.x, b = blockIdx.y;
    const float* row = g_cc + (size_t)b*CHN*CHN + (size_t)c*CHN;
    const int d = threadIdx.x, lane = d & 31, w = d >> 5;
    __shared__ float smax[8];
    __shared__ float ssum[8];

    float v = row[d];
    float m = v;
    #pragma unroll
    for (int o = 16; o; o >>= 1) m = fmaxf(m, __shfl_xor_sync(0xffffffffu, m, o));
    if (lane == 0) smax[w] = m;
    __syncthreads();
    float M = smax[0];
    #pragma unroll
    for (int i = 1; i < 8; i++) M = fmaxf(M, smax[i]);

    float e = expf(v - M);
    float su = e;
    #pragma unroll
    for (int o = 16; o; o >>= 1) su += __shfl_xor_sync(0xffffffffu, su, o);
    if (lane == 0) ssum[w] = su;
    __syncthreads();
    float S = 0.f;
    #pragma unroll
    for (int i = 0; i < 8; i++) S += ssum[i];

    float vv = e / S + ((d == c) ? 1.f : 0.f);
    __nv_bfloat16 hi = __float2bfloat16(vv);
    float lo = vv - __bfloat162float(hi);
    size_t idxT = ((size_t)b*CHN + d)*CHN + c;   // transposed: [d][c]
    g_ccT_hi[idxT] = hi;
    g_ccT_lo[idxT] = __float2bfloat16(lo);
}

// ============================================================
extern "C" void kernel_launch(void* const* d_in, const int* in_sizes, int n_in,
                              void* d_out, int out_size) {
    (void)in_sizes; (void)n_in; (void)out_size;
    const float* x  = (const float*)d_in[0];
    const float* Wq = (const float*)d_in[1];
    const float* bq = (const float*)d_in[2];
    const float* Wk = (const float*)d_in[3];
    const float* bk = (const float*)d_in[4];
    float* out = (float*)d_out;

    static int attr_done = 0;
    if (!attr_done) {
        cudaFuncSetAttribute(gram_mma_kernel, cudaFuncAttributeMaxDynamicSharedMemorySize, SMEM_MMA);
        cudaFuncSetAttribute(out_mma_kernel,  cudaFuncAttributeMaxDynamicSharedMemorySize, SMEM_MMA);
        attr_done = 1;
    }

    zero_kernel    <<<(BATCH*CHN*CHN + 255)/256, 256>>>();
    convert_kernel <<<NELEM/(256*8), 256>>>(x);
    gram_mma_kernel<<<dim3(3, BATCH, 16), 256, SMEM_MMA>>>();
    pmat_kernel    <<<dim3(4, 4, BATCH), 256>>>(Wq);
    qsks_kernel    <<<dim3(32, BATCH), 256>>>(Wq, Wk);
    scores_kernel  <<<dim3(4, 4, BATCH), 256>>>(Wk, bq, bk);
    softmax_kernel <<<dim3(CHN, BATCH), 256>>>();
    out_mma_kernel <<<dim3(2, 128, BATCH), 256, SMEM_MMA>>>(out);
}